// round 16
// baseline (speedup 1.0000x reference)
#include <cuda_runtime.h>

// out[p, :] = cumsum(W, axis=1)[:, x[p]] + b, p in [0, 8192*200)
// x: int32 (NPOS), W: fp32 (64,129) row-major, b: fp32 (64), out: fp32 (NPOS*64)

#define F1 129                  // num_feature + 1
#define D  64                   // vector dim
#define NPOS (8192 * 200)       // 1,638,400 positions (divisible by 32)
#define TPB 256
#define WARPS_PB (TPB / 32)

__global__ void __launch_bounds__(TPB, 6)
embed_kernel(const int* __restrict__ x,
             const float* __restrict__ W,
             const float* __restrict__ b,
             float* __restrict__ out) {
    // tab[c*64 + d] = b[d] + sum_{j<=c} W[d*F1 + j]; 33,024 B
    __shared__ float tab[F1 * D];
    __shared__ float carry[4][D];          // per-dim segment sums (1 KB)

    // ---- parallel table build: 256 threads = 4 segments x 64 dims ----
    {
        const int t   = threadIdx.x;
        const int d   = t & 63;
        const int seg = t >> 6;                 // 0..3
        const int start = seg * 33;             // 0,33,66,99
        const int cnt   = (seg == 3) ? 30 : 33;
        const float* wrow = W + d * F1 + start;

        // Pass 1: stage raw W into tab + segment sum (batched -> ~1 round trip)
        float s = 0.f;
        int j = 0;
        for (; j + 8 <= cnt; j += 8) {
            float v[8];
            #pragma unroll
            for (int u = 0; u < 8; ++u) v[u] = __ldg(&wrow[j + u]);
            #pragma unroll
            for (int u = 0; u < 8; ++u) {
                s += v[u];
                tab[(start + j + u) * D + d] = v[u];
            }
        }
        for (; j < cnt; ++j) {
            float v = __ldg(&wrow[j]);
            s += v;
            tab[(start + j) * D + d] = v;
        }
        carry[seg][d] = s;
        __syncthreads();

        // Pass 2: carry-in + short in-smem prefix chain over this segment
        float p = __ldg(&b[d]);
        #pragma unroll
        for (int q = 0; q < 3; ++q)
            if (q < seg) p += carry[q][d];
        for (j = 0; j < cnt; ++j) {
            p += tab[(start + j) * D + d];
            tab[(start + j) * D + d] = p;
        }
        __syncthreads();
    }

    const float4* tab4 = reinterpret_cast<const float4*>(tab);

    // ---- gather/store loop: byte-identical to the 75.2us champion ----
    const int lane   = threadIdx.x & 31;
    const int lane15 = lane & 15;          // which float4 within the 64-float row
    const int half   = lane >> 4;          // 0/1: which of each pair of positions
    const int warp   = threadIdx.x >> 5;

    const int gwarp  = blockIdx.x * WARPS_PB + warp;
    const int nwarps = gridDim.x * WARPS_PB;
    const int stride = nwarps * 32;        // positions per warp per outer iter
    float4* __restrict__ o4 = reinterpret_cast<float4*>(out);

    int base = gwarp * 32;
    if (base >= NPOS) return;

    int xv = x[base + lane];                       // coalesced 128B load
    #pragma unroll 1
    for (; base < NPOS; base += stride) {
        // ---- Phase A: all 16 broadcast indices up front (independent) ----
        int idx[16];
        #pragma unroll
        for (int k = 0; k < 16; ++k)
            idx[k] = __shfl_sync(0xffffffffu, xv, 2 * k + half) * (D / 4) + lane15;

        // prefetch next iteration's x-vector off the critical path
        const int nbase = base + stride;
        int xv_next = 0;
        if (nbase < NPOS) xv_next = x[nbase + lane];

        // ---- Phase B: 16 independent LDS.128 -> STG.128 chains ----
        float4* wbase = o4 + ((size_t)base + half) * (D / 4) + lane15;
        #pragma unroll
        for (int k = 0; k < 16; ++k) {
            const float4 v = tab4[idx[k]];
            __stcs(wbase + k * 2 * (D / 4), v);    // k*512 bytes, streaming
        }
        xv = xv_next;
    }
}

extern "C" void kernel_launch(void* const* d_in, const int* in_sizes, int n_in,
                              void* d_out, int out_size) {
    const int*   x = (const int*)  d_in[0];
    const float* W = (const float*)d_in[1];
    const float* b = (const float*)d_in[2];
    float*     out = (float*)d_out;

    // Persistent grid: 152 SMs * 6 CTAs (smem-limited at 34KB/CTA)
    const int grid = 152 * 6;
    embed_kernel<<<grid, TPB>>>(x, W, b, out);
}

// round 17
// speedup vs baseline: 1.0608x; 1.0608x over previous
#include <cuda_runtime.h>

// out[p, :] = cumsum(W, axis=1)[:, x[p]] + b, p in [0, 8192*200)
// x: int32 (NPOS), W: fp32 (64,129) row-major, b: fp32 (64), out: fp32 (NPOS*64)

#define F1 129                  // num_feature + 1
#define D  64                   // vector dim
#define NPOS (8192 * 200)       // 1,638,400 positions (divisible by 32)
#define TPB 256
#define WARPS_PB (TPB / 32)

__global__ void __launch_bounds__(TPB, 6)
embed_kernel(const int* __restrict__ x,
             const float* __restrict__ W,
             const float* __restrict__ b,
             float* __restrict__ out) {
    // Shared table: tab[c*64 + d] = b[d] + sum_{j<=c} W[d*F1 + j]; 33,024 B
    __shared__ float tab[F1 * D];

    // ---- fused table build (threads 0..63): batched loads keep the ----
    // ---- FADD chain, not memory latency, on the critical path.     ----
    // ---- Hidden under the 912-CTA launch ramp (measured R16).      ----
    const int t = threadIdx.x;
    if (t < D) {
        const float* wrow = W + t * F1;
        float s = b[t];
        #pragma unroll 1
        for (int c0 = 0; c0 < 128; c0 += 8) {
            float v[8];
            #pragma unroll
            for (int j = 0; j < 8; ++j) v[j] = __ldg(&wrow[c0 + j]);
            #pragma unroll
            for (int j = 0; j < 8; ++j) {
                s += v[j];
                tab[(c0 + j) * D + t] = s;
            }
        }
        s += __ldg(&wrow[128]);
        tab[128 * D + t] = s;
    }
    __syncthreads();

    const float4* tab4 = reinterpret_cast<const float4*>(tab);

    const int lane   = threadIdx.x & 31;
    const int lane15 = lane & 15;          // which float4 within the 64-float row
    const int half   = lane >> 4;          // 0/1: which of each pair of positions
    const int warp   = threadIdx.x >> 5;

    const int gwarp  = blockIdx.x * WARPS_PB + warp;
    const int nwarps = gridDim.x * WARPS_PB;
    const int stride = nwarps * 32;        // positions per warp per outer iter
    float4* __restrict__ o4 = reinterpret_cast<float4*>(out);

    int base = gwarp * 32;
    if (base >= NPOS) return;

    int xv = x[base + lane];                       // coalesced 128B load
    #pragma unroll 1
    for (; base < NPOS; base += stride) {
        // ---- Phase A: all 16 broadcast indices up front (independent) ----
        int idx[16];
        #pragma unroll
        for (int k = 0; k < 16; ++k)
            idx[k] = __shfl_sync(0xffffffffu, xv, 2 * k + half) * (D / 4) + lane15;

        // prefetch next iteration's x-vector off the critical path
        const int nbase = base + stride;
        int xv_next = 0;
        if (nbase < NPOS) xv_next = x[nbase + lane];

        // ---- Phase B: 16 independent LDS.128 -> STG.128 chains.       ----
        // Store addresses differ only by k*512B -> immediate offsets off
        // a single base register; ptxas software-pipelines deeply.
        float4* wbase = o4 + ((size_t)base + half) * (D / 4) + lane15;
        #pragma unroll
        for (int k = 0; k < 16; ++k) {
            const float4 v = tab4[idx[k]];
            __stcs(wbase + k * 2 * (D / 4), v);    // k*512 bytes, streaming
        }
        xv = xv_next;
    }
}

extern "C" void kernel_launch(void* const* d_in, const int* in_sizes, int n_in,
                              void* d_out, int out_size) {
    const int*   x = (const int*)  d_in[0];
    const float* W = (const float*)d_in[1];
    const float* b = (const float*)d_in[2];
    float*     out = (float*)d_out;

    // Persistent grid: 152 SMs * 6 CTAs (smem-limited at 33KB/CTA)
    const int grid = 152 * 6;
    embed_kernel<<<grid, TPB>>>(x, W, b, out);
}